// round 3
// baseline (speedup 1.0000x reference)
#include <cuda_runtime.h>

#define NSEG 128
#define EDIM 128
#define NHEAD 4
#define WARPS_PER_BLK 8
#define NBLK 592   // 4 blocks/SM * 148 SMs -> single wave

__device__ float g_s[NSEG * NHEAD];
__device__ float g_acc[NSEG * NHEAD * EDIM];
__device__ int   g_is64;
__device__ unsigned int g_done;

// Zero accumulators + reset completion counter + detect batch dtype.
__global__ void zero_kernel(const int* __restrict__ b32, int N) {
    int i = blockIdx.x * blockDim.x + threadIdx.x;
    if (i < NSEG * NHEAD * EDIM) g_acc[i] = 0.0f;
    if (i < NSEG * NHEAD)        g_s[i]   = 0.0f;
    if (i == 0) {
        g_done = 0;
        // int64 (LE): int32 view at tail odd indices holds zero high words.
        int a = b32[N - 1];
        int b = (N >= 3) ? b32[N - 3] : 1;
        int c = (N >= 5) ? b32[N - 5] : 1;
        g_is64 = (a == 0 && b == 0 && c == 0) ? 1 : 0;
    }
}

template <typename IT>
__device__ __forceinline__ void warp_loop(
    const float4* __restrict__ x, const IT* __restrict__ batch,
    int beg, int end, int lane)
{
    const int b0 = lane & 1;
    const int b1 = (lane >> 1) & 1;
    const int c  = 2 * b0 + b1;          // head class owned by this lane
    // accumulator j -> head: {c, c^2, c^1, c^3}
    const int h0 = c, h1 = c ^ 2, h2 = c ^ 1, h3 = c ^ 3;

    // weights: lane l holds columns 4l..4l+3 per head
    extern __device__ float g_s[], g_acc[];
    const float4* w4 = nullptr; // set by caller via global symbol trick? no — pass below
    (void)w4;

    float accS = 0.0f;
    float4 a0 = make_float4(0,0,0,0), a1 = a0, a2 = a0, a3 = a0;

    // load weights
    // (weights pointer is stored in constant-like global below)
    extern __constant__ float c_w[]; (void)c_w;
    // -- replaced: weights passed through global pointer --
    // (actual implementation inline in kernel; this function unused)
    (void)x; (void)batch; (void)beg; (void)end; (void)lane;
    (void)accS; (void)a0; (void)a1; (void)a2; (void)a3;
    (void)h0; (void)h1; (void)h2; (void)h3;
}

__global__ __launch_bounds__(256) void att_kernel(
    const float4* __restrict__ x,        // [N, 32] float4 view of [N,128]
    const float4* __restrict__ w,        // [4, 32]
    const void*   __restrict__ batch,
    float* __restrict__ out,
    int N, int rpw)
{
    const int lane = threadIdx.x & 31;
    const int wid  = threadIdx.x >> 5;
    const int gw   = blockIdx.x * WARPS_PER_BLK + wid;
    const int is64 = g_is64;

    const int b1v = (lane >> 1) & 1;
    const int c   = 2 * (lane & 1) + b1v;       // head class of this lane
    const int h0 = c, h1 = c ^ 2, h2 = c ^ 1, h3 = c ^ 3;

    int beg = gw * rpw;
    int end = beg + rpw; if (end > N) end = N;

    if (beg < end) {
        float4 wv0 = w[0 * 32 + lane];
        float4 wv1 = w[1 * 32 + lane];
        float4 wv2 = w[2 * 32 + lane];
        float4 wv3 = w[3 * 32 + lane];

        float  accS = 0.0f;
        float4 a0 = make_float4(0,0,0,0), a1 = a0, a2 = a0, a3 = a0;

        const long long* b64 = (const long long*)batch;
        const int*       b32 = (const int*)batch;

        int cur = (is64 ? (int)b64[beg] : b32[beg]) & (NSEG - 1);

        for (int n = beg; n < end; ++n) {
            int seg = (is64 ? (int)b64[n] : b32[n]) & (NSEG - 1);
            if (seg != cur) {
                // flush finished segment
                if (lane < 4) atomicAdd(&g_s[cur * NHEAD + c], accS);
                float* base = &g_acc[cur * NHEAD * EDIM + lane * 4];
                atomicAdd(base + h0 * EDIM + 0, a0.x);
                atomicAdd(base + h0 * EDIM + 1, a0.y);
                atomicAdd(base + h0 * EDIM + 2, a0.z);
                atomicAdd(base + h0 * EDIM + 3, a0.w);
                atomicAdd(base + h1 * EDIM + 0, a1.x);
                atomicAdd(base + h1 * EDIM + 1, a1.y);
                atomicAdd(base + h1 * EDIM + 2, a1.z);
                atomicAdd(base + h1 * EDIM + 3, a1.w);
                atomicAdd(base + h2 * EDIM + 0, a2.x);
                atomicAdd(base + h2 * EDIM + 1, a2.y);
                atomicAdd(base + h2 * EDIM + 2, a2.z);
                atomicAdd(base + h2 * EDIM + 3, a2.w);
                atomicAdd(base + h3 * EDIM + 0, a3.x);
                atomicAdd(base + h3 * EDIM + 1, a3.y);
                atomicAdd(base + h3 * EDIM + 2, a3.z);
                atomicAdd(base + h3 * EDIM + 3, a3.w);
                accS = 0.0f;
                a0 = make_float4(0,0,0,0); a1 = a0; a2 = a0; a3 = a0;
                cur = seg;
            }

            float4 xv = x[n * 32 + lane];

            // per-lane partial dots
            float p0 = xv.x*wv0.x + xv.y*wv0.y + xv.z*wv0.z + xv.w*wv0.w;
            float p1 = xv.x*wv1.x + xv.y*wv1.y + xv.z*wv1.z + xv.w*wv1.w;
            float p2 = xv.x*wv2.x + xv.y*wv2.y + xv.z*wv2.z + xv.w*wv2.w;
            float p3 = xv.x*wv3.x + xv.y*wv3.y + xv.z*wv3.z + xv.w*wv3.w;

            // level 1 (offset 1): evens keep heads {0,1}, odds keep {2,3}
            float t0 = (lane & 1) ? p0 : p2;
            float t1 = (lane & 1) ? p1 : p3;
            t0 = __shfl_xor_sync(0xffffffffu, t0, 1);
            t1 = __shfl_xor_sync(0xffffffffu, t1, 1);
            float u0 = ((lane & 1) ? p2 : p0) + t0;   // head 2*b0
            float u1 = ((lane & 1) ? p3 : p1) + t1;   // head 2*b0+1

            // level 2 (offset 2): keep u_{b1} -> head c
            float t = b1v ? u0 : u1;
            t = __shfl_xor_sync(0xffffffffu, t, 2);
            float E = (b1v ? u1 : u0) + t;

            // levels 4, 8, 16
            E += __shfl_xor_sync(0xffffffffu, E, 4);
            E += __shfl_xor_sync(0xffffffffu, E, 8);
            E += __shfl_xor_sync(0xffffffffu, E, 16);

            // exp of the single owned head
            float e = __expf(E);

            // regather the other 3 heads
            float fA = __shfl_xor_sync(0xffffffffu, e, 1);   // head c^2
            float fB = __shfl_xor_sync(0xffffffffu, e, 2);   // head c^1
            float fC = __shfl_xor_sync(0xffffffffu, fA, 2);  // head c^3

            accS += e;
            a0.x += e  * xv.x; a0.y += e  * xv.y; a0.z += e  * xv.z; a0.w += e  * xv.w;
            a1.x += fA * xv.x; a1.y += fA * xv.y; a1.z += fA * xv.z; a1.w += fA * xv.w;
            a2.x += fB * xv.x; a2.y += fB * xv.y; a2.z += fB * xv.z; a2.w += fB * xv.w;
            a3.x += fC * xv.x; a3.y += fC * xv.y; a3.z += fC * xv.z; a3.w += fC * xv.w;
        }

        // final flush
        if (lane < 4) atomicAdd(&g_s[cur * NHEAD + c], accS);
        float* base = &g_acc[cur * NHEAD * EDIM + lane * 4];
        atomicAdd(base + h0 * EDIM + 0, a0.x);
        atomicAdd(base + h0 * EDIM + 1, a0.y);
        atomicAdd(base + h0 * EDIM + 2, a0.z);
        atomicAdd(base + h0 * EDIM + 3, a0.w);
        atomicAdd(base + h1 * EDIM + 0, a1.x);
        atomicAdd(base + h1 * EDIM + 1, a1.y);
        atomicAdd(base + h1 * EDIM + 2, a1.z);
        atomicAdd(base + h1 * EDIM + 3, a1.w);
        atomicAdd(base + h2 * EDIM + 0, a2.x);
        atomicAdd(base + h2 * EDIM + 1, a2.y);
        atomicAdd(base + h2 * EDIM + 2, a2.z);
        atomicAdd(base + h2 * EDIM + 3, a2.w);
        atomicAdd(base + h3 * EDIM + 0, a3.x);
        atomicAdd(base + h3 * EDIM + 1, a3.y);
        atomicAdd(base + h3 * EDIM + 2, a3.z);
        atomicAdd(base + h3 * EDIM + 3, a3.w);
    }

    // ---- inline finalize: last block to finish does the reduction ----
    __shared__ int s_last;
    __threadfence();
    __syncthreads();
    if (threadIdx.x == 0) {
        unsigned int prev = atomicAdd(&g_done, 1u);
        s_last = (prev == (unsigned int)(gridDim.x - 1)) ? 1 : 0;
    }
    __syncthreads();
    if (s_last) {
        for (int i = threadIdx.x; i < NSEG * EDIM; i += blockDim.x) {
            int b = i >> 7;        // segment
            int e = i & 127;       // embed dim
            float r = 0.0f;
#pragma unroll
            for (int h = 0; h < NHEAD; ++h) {
                float av = __ldcg(&g_acc[(b * NHEAD + h) * EDIM + e]);
                float sv = __ldcg(&g_s[b * NHEAD + h]);
                r += av / sv;
            }
            out[i] = r * (1.0f / NHEAD);
        }
    }
}

extern "C" void kernel_launch(void* const* d_in, const int* in_sizes, int n_in,
                              void* d_out, int out_size) {
    const float* x     = (const float*)d_in[0];
    const float* w     = (const float*)d_in[1];
    const void*  batch = d_in[2];

    int N = in_sizes[0] / EDIM;
    int warps = NBLK * WARPS_PER_BLK;
    int rpw = (N + warps - 1) / warps;

    zero_kernel<<<(NSEG * NHEAD * EDIM + 255) / 256, 256>>>((const int*)batch, N);
    att_kernel<<<NBLK, 256>>>((const float4*)x, (const float4*)w, batch,
                              (float*)d_out, N, rpw);
}